// round 2
// baseline (speedup 1.0000x reference)
#include <cuda_runtime.h>
#include <math.h>

#define N_MOLS 8192
#define N_ATOMS 98304
#define N_BONDS 196608
#define HIDDEN 300
#define HEADS 4
#define DEPTH 6
#define MASTER_DIM 600
#define ATOM_FDIM 133
#define BOND_FDIM 147
#define MAX_NB 6

#define NB1 (N_BONDS + 1)
#define NA1 (N_ATOMS + 1)
#define H4 (HEADS * HIDDEN)          /* 1200 */
#define AIN (ATOM_FDIM + HIDDEN)     /* 433 */
#define CHUNK 65664                  /* 513*128; 3 chunks cover NB1 */

// ---------------------------------------------------------------------------
// Scratch (device globals; ~1.07GB total to stay far below the 2GB
// host-shadow relocation limit)
// ---------------------------------------------------------------------------
__device__ float g_binput[(size_t)NB1 * HIDDEN];            // 236MB
__device__ float g_msg[(size_t)NB1 * HIDDEN];               // 236MB
__device__ float g_neimsg[(size_t)NB1 * HIDDEN];            // 236MB
__device__ float g_qc[(size_t)CHUNK * H4];                  // 315MB (q/comps chunk; later ainp+atomh)
__device__ float g_molmean[(size_t)N_MOLS * HIDDEN];
__device__ float g_master[(size_t)N_MOLS * MASTER_DIM];
__device__ float g_mm[(size_t)N_MOLS * HIDDEN];

__device__ float g_WiT[BOND_FDIM * HIDDEN];
__device__ float g_Wq[HIDDEN * H4];
__device__ float g_WhT[H4 * HIDDEN];
__device__ float g_WmiT[HIDDEN * MASTER_DIM];
__device__ float g_WmoT[MASTER_DIM * HIDDEN];
__device__ float g_WoT[AIN * HIDDEN];
__device__ float g_mmpad[HIDDEN];

// static_assert chunk buffer can host ainp + atomh for the readout phase
static_assert((size_t)CHUNK * H4 >= (size_t)NA1 * AIN + (size_t)NA1 * HIDDEN, "arena");

// ---------------------------------------------------------------------------
// Generic SGEMM: C[M,N] = A[M,K] @ B[K,N] (+bias) (+relu)
// BM=128, BN=64, BK=16, 128 threads, 8x8 per thread, fma.rn.f32x2 inner loop.
// If C2 != nullptr: C gets raw pre-activation, C2 gets relu(raw).
// ---------------------------------------------------------------------------
__global__ void __launch_bounds__(128) sgemm_kernel(
    const float* __restrict__ A, const float* __restrict__ B,
    const float* __restrict__ bias,
    float* __restrict__ C, float* __restrict__ C2,
    int M, int N, int K, int do_relu)
{
    __shared__ __align__(16) float  As[16][132];   // [k][m], padded stride
    __shared__ __align__(16) float2 Bs[16][64];    // duplicated pairs (v,v)

    const int tid = threadIdx.x;
    const int bm = blockIdx.y * 128;
    const int bn = blockIdx.x * 64;
    const int m0 = (tid >> 3) * 8;   // 16 groups of 8 rows
    const int n0 = (tid & 7) * 8;    // 8 groups of 8 cols

    unsigned long long acc[4][8];
#pragma unroll
    for (int i = 0; i < 4; ++i)
#pragma unroll
        for (int j = 0; j < 8; ++j) acc[i][j] = 0ull;

    const int a_k = tid & 15;
    const int a_m = tid >> 4;    // 0..7
    const int b_n = tid & 63;
    const int b_k = tid >> 6;    // 0..1

    for (int k0 = 0; k0 < K; k0 += 16) {
#pragma unroll
        for (int i = 0; i < 16; ++i) {
            int m = a_m + i * 8;
            int gm = bm + m, gk = k0 + a_k;
            float v = 0.f;
            if (gm < M && gk < K) v = A[(size_t)gm * K + gk];
            As[a_k][m] = v;
        }
#pragma unroll
        for (int i = 0; i < 8; ++i) {
            int kk = b_k + i * 2;
            int gk = k0 + kk, gn = bn + b_n;
            float v = 0.f;
            if (gk < K && gn < N) v = B[(size_t)gk * N + gn];
            Bs[kk][b_n] = make_float2(v, v);
        }
        __syncthreads();
#pragma unroll
        for (int k = 0; k < 16; ++k) {
            ulonglong2 a01 = *reinterpret_cast<const ulonglong2*>(&As[k][m0]);
            ulonglong2 a23 = *reinterpret_cast<const ulonglong2*>(&As[k][m0 + 4]);
            unsigned long long ap[4] = {a01.x, a01.y, a23.x, a23.y};
            const ulonglong2* bl = reinterpret_cast<const ulonglong2*>(&Bs[k][n0]);
            ulonglong2 b01 = bl[0], b23 = bl[1], b45 = bl[2], b67 = bl[3];
            unsigned long long bp[8] = {b01.x, b01.y, b23.x, b23.y,
                                        b45.x, b45.y, b67.x, b67.y};
#pragma unroll
            for (int i = 0; i < 4; ++i)
#pragma unroll
                for (int j = 0; j < 8; ++j)
                    asm("fma.rn.f32x2 %0, %1, %2, %3;"
                        : "=l"(acc[i][j])
                        : "l"(ap[i]), "l"(bp[j]), "l"(acc[i][j]));
        }
        __syncthreads();
    }

#pragma unroll
    for (int i = 0; i < 4; ++i) {
        int gm = bm + m0 + 2 * i;
#pragma unroll
        for (int j = 0; j < 8; ++j) {
            int gn = bn + n0 + j;
            if (gn >= N) continue;
            unsigned long long u = acc[i][j];
            float vx = __uint_as_float((unsigned)(u & 0xffffffffull));
            float vy = __uint_as_float((unsigned)(u >> 32));
            if (bias) { float bv = bias[gn]; vx += bv; vy += bv; }
            if (C2) {
                if (gm < M) {
                    C[(size_t)gm * N + gn] = vx;
                    C2[(size_t)gm * N + gn] = fmaxf(vx, 0.f);
                }
                if (gm + 1 < M) {
                    C[(size_t)(gm + 1) * N + gn] = vy;
                    C2[(size_t)(gm + 1) * N + gn] = fmaxf(vy, 0.f);
                }
            } else {
                float ox = do_relu ? fmaxf(vx, 0.f) : vx;
                float oy = do_relu ? fmaxf(vy, 0.f) : vy;
                if (gm < M)     C[(size_t)gm * N + gn] = ox;
                if (gm + 1 < M) C[(size_t)(gm + 1) * N + gn] = oy;
            }
        }
    }
}

// ---------------------------------------------------------------------------
// Weight repacking
// ---------------------------------------------------------------------------
__global__ void transpose_kernel(const float* __restrict__ in,
                                 float* __restrict__ out, int R, int C)
{
    int i = blockIdx.x * 256 + threadIdx.x;
    if (i >= R * C) return;
    int r = i / C, c = i - r * C;
    out[(size_t)c * R + r] = in[i];
}

// W_ma[h,e,d] -> Wq[e, h*300+d]
__global__ void wma_repack_kernel(const float* __restrict__ W_ma)
{
    int i = blockIdx.x * 256 + threadIdx.x;
    if (i >= HEADS * HIDDEN * HIDDEN) return;
    int h = i / (HIDDEN * HIDDEN);
    int r = i - h * (HIDDEN * HIDDEN);
    int e = r / HIDDEN, d = r - e * HIDDEN;
    g_Wq[(size_t)e * H4 + h * HIDDEN + d] = W_ma[i];
}

// mm_pad[d] = sum_k relu(b_mi[k]) * W_mo[d,k]  (constant padding-row master term)
__global__ void mmpad_kernel(const float* __restrict__ b_mi)
{
    int d = threadIdx.x;
    if (d >= HIDDEN) return;
    float s = 0.f;
    for (int k = 0; k < MASTER_DIM; ++k) {
        float m = fmaxf(b_mi[k], 0.f);
        s += m * g_WmoT[k * HIDDEN + d];
    }
    g_mmpad[d] = s;
}

// ---------------------------------------------------------------------------
// Attention for a chunk of bonds: per bond b (global), scores[h,n] =
// q[b,h,:] . msg[bgraph[b,n],:], softmax over n,
// comps[b,h*300+d] = sum_n attn * nei[n,d].
// q and comps share the same chunk buffer (read fully into smem first).
// One block (128 threads = 4 warps, one warp per head) per bond.
// ---------------------------------------------------------------------------
__global__ void __launch_bounds__(128) attn_kernel(
    const int* __restrict__ bgraph, const float* __restrict__ msg,
    float* __restrict__ qc, int base, int count)
{
    int local = blockIdx.x;
    if (local >= count) return;
    int b = base + local;
    int tid = threadIdx.x;
    __shared__ float nei[MAX_NB][HIDDEN];
    __shared__ float qsh[H4];
    __shared__ int nb[MAX_NB];

    if (tid < MAX_NB) nb[tid] = bgraph[(size_t)b * MAX_NB + tid];
    __syncthreads();

    for (int i = tid; i < MAX_NB * HIDDEN; i += 128) {
        int n = i / HIDDEN, d = i - n * HIDDEN;
        nei[n][d] = msg[(size_t)nb[n] * HIDDEN + d];
    }
    for (int i = tid; i < H4; i += 128) qsh[i] = qc[(size_t)local * H4 + i];
    __syncthreads();

    int w = tid >> 5, lane = tid & 31;
    float part[MAX_NB];
#pragma unroll
    for (int n = 0; n < MAX_NB; ++n) part[n] = 0.f;
    for (int d = lane; d < HIDDEN; d += 32) {
        float qv = qsh[w * HIDDEN + d];
#pragma unroll
        for (int n = 0; n < MAX_NB; ++n) part[n] += qv * nei[n][d];
    }
#pragma unroll
    for (int n = 0; n < MAX_NB; ++n)
#pragma unroll
        for (int off = 16; off > 0; off >>= 1)
            part[n] += __shfl_xor_sync(0xffffffffu, part[n], off);

    float mx = part[0];
#pragma unroll
    for (int n = 1; n < MAX_NB; ++n) mx = fmaxf(mx, part[n]);
    float e[MAX_NB], den = 0.f;
#pragma unroll
    for (int n = 0; n < MAX_NB; ++n) { e[n] = __expf(part[n] - mx); den += e[n]; }
    float inv = 1.f / den;

    for (int d = lane; d < HIDDEN; d += 32) {
        float s = 0.f;
#pragma unroll
        for (int n = 0; n < MAX_NB; ++n) s += e[n] * nei[n][d];
        qc[(size_t)local * H4 + w * HIDDEN + d] = s * inv;
    }
}

// ---------------------------------------------------------------------------
// Segment mean: one block per molecule; ids sorted; vals has +1 padding row.
// ---------------------------------------------------------------------------
__global__ void segmean_kernel(const float* __restrict__ vals,
                               const int* __restrict__ ids, int nitems, int D,
                               float* __restrict__ out)
{
    int m = blockIdx.x;
    int lo = 0, hi = nitems;
    while (lo < hi) { int mid = (lo + hi) >> 1; if (ids[mid] < m) lo = mid + 1; else hi = mid; }
    int start = lo;
    hi = nitems;
    while (lo < hi) { int mid = (lo + hi) >> 1; if (ids[mid] < m + 1) lo = mid + 1; else hi = mid; }
    int end = lo;
    int cnt = end - start;
    float inv = 1.f / (float)(cnt > 1 ? cnt : 1);
    for (int d = threadIdx.x; d < D; d += blockDim.x) {
        float s = 0.f;
        for (int i = start; i < end; ++i) s += vals[(size_t)(i + 1) * D + d];
        out[(size_t)m * D + d] = s * inv;
    }
}

// msg = relu(binput + nei_msg + mm[bond2mol] + b_mo); row 0 uses mm_pad
__global__ void update_kernel(const int* __restrict__ bond2mol,
                              const float* __restrict__ b_mo)
{
    size_t idx = (size_t)blockIdx.x * 256 + threadIdx.x;
    if (idx >= (size_t)NB1 * HIDDEN) return;
    int b = (int)(idx / HIDDEN);
    int d = (int)(idx - (size_t)b * HIDDEN);
    float mmv = (b == 0) ? g_mmpad[d]
                         : g_mm[(size_t)bond2mol[b - 1] * HIDDEN + d];
    float v = g_binput[idx] + g_neimsg[idx] + mmv + b_mo[d];
    g_msg[idx] = fmaxf(v, 0.f);
}

// ainp = [fatoms | sum_n msg[agraph[a,n]]]
__global__ void __launch_bounds__(128) atom_gather_kernel(
    const float* __restrict__ fatoms, const int* __restrict__ agraph,
    float* __restrict__ ainp)
{
    int a = blockIdx.x;
    __shared__ int nb[MAX_NB];
    if (threadIdx.x < MAX_NB) nb[threadIdx.x] = agraph[(size_t)a * MAX_NB + threadIdx.x];
    __syncthreads();
    for (int c = threadIdx.x; c < ATOM_FDIM; c += 128)
        ainp[(size_t)a * AIN + c] = fatoms[(size_t)a * ATOM_FDIM + c];
    for (int d = threadIdx.x; d < HIDDEN; d += 128) {
        float s = 0.f;
#pragma unroll
        for (int n = 0; n < MAX_NB; ++n) s += g_msg[(size_t)nb[n] * HIDDEN + d];
        ainp[(size_t)a * AIN + ATOM_FDIM + d] = s;
    }
}

// ---------------------------------------------------------------------------
// Host launch
// ---------------------------------------------------------------------------
static inline int cdiv(int a, int b) { return (a + b - 1) / b; }

extern "C" void kernel_launch(void* const* d_in, const int* in_sizes, int n_in,
                              void* d_out, int out_size)
{
    const float* fatoms   = (const float*)d_in[0];
    const float* fbonds   = (const float*)d_in[1];
    const int*   agraph   = (const int*)d_in[2];
    const int*   bgraph   = (const int*)d_in[3];
    const int*   atom2mol = (const int*)d_in[4];
    const int*   bond2mol = (const int*)d_in[5];
    const float* W_i  = (const float*)d_in[6];
    const float* W_h  = (const float*)d_in[7];
    const float* W_ma = (const float*)d_in[8];
    const float* W_mi = (const float*)d_in[9];
    const float* b_mi = (const float*)d_in[10];
    const float* W_mo = (const float*)d_in[11];
    const float* b_mo = (const float*)d_in[12];
    const float* W_o  = (const float*)d_in[13];
    const float* b_o  = (const float*)d_in[14];
    float* out = (float*)d_out;

    float *binput, *msg, *neimsg, *qc, *molmean, *master, *mm;
    float *WiT, *Wq, *WhT, *WmiT, *WmoT, *WoT;
    cudaGetSymbolAddress((void**)&binput, g_binput);
    cudaGetSymbolAddress((void**)&msg, g_msg);
    cudaGetSymbolAddress((void**)&neimsg, g_neimsg);
    cudaGetSymbolAddress((void**)&qc, g_qc);
    cudaGetSymbolAddress((void**)&molmean, g_molmean);
    cudaGetSymbolAddress((void**)&master, g_master);
    cudaGetSymbolAddress((void**)&mm, g_mm);
    cudaGetSymbolAddress((void**)&WiT, g_WiT);
    cudaGetSymbolAddress((void**)&Wq, g_Wq);
    cudaGetSymbolAddress((void**)&WhT, g_WhT);
    cudaGetSymbolAddress((void**)&WmiT, g_WmiT);
    cudaGetSymbolAddress((void**)&WmoT, g_WmoT);
    cudaGetSymbolAddress((void**)&WoT, g_WoT);

    float* ainp  = qc;                                   // reuse chunk arena
    float* atomh = qc + (size_t)NA1 * AIN;

    // repack weights
    transpose_kernel<<<cdiv(HIDDEN * BOND_FDIM, 256), 256>>>(W_i, WiT, HIDDEN, BOND_FDIM);
    transpose_kernel<<<cdiv(HIDDEN * H4, 256), 256>>>(W_h, WhT, HIDDEN, H4);
    wma_repack_kernel<<<cdiv(HEADS * HIDDEN * HIDDEN, 256), 256>>>(W_ma);
    transpose_kernel<<<cdiv(MASTER_DIM * HIDDEN, 256), 256>>>(W_mi, WmiT, MASTER_DIM, HIDDEN);
    transpose_kernel<<<cdiv(HIDDEN * MASTER_DIM, 256), 256>>>(W_mo, WmoT, HIDDEN, MASTER_DIM);
    transpose_kernel<<<cdiv(HIDDEN * AIN, 256), 256>>>(W_o, WoT, HIDDEN, AIN);
    mmpad_kernel<<<1, 320>>>(b_mi);

    // binput = fbonds @ W_i^T ; msg = relu(binput)
    {
        dim3 grid(cdiv(HIDDEN, 64), cdiv(NB1, 128));
        sgemm_kernel<<<grid, 128>>>(fbonds, WiT, nullptr, binput, msg,
                                    NB1, HIDDEN, BOND_FDIM, 0);
    }

    for (int it = 0; it < DEPTH - 1; ++it) {
        // chunked: q -> attn -> nei_msg, reusing the 315MB qc buffer
        for (int base = 0; base < NB1; base += CHUNK) {
            int rows = NB1 - base; if (rows > CHUNK) rows = CHUNK;
            // q_chunk = msg[base:base+rows] @ Wq   [rows x 1200]
            {
                dim3 grid(cdiv(H4, 64), cdiv(rows, 128));
                sgemm_kernel<<<grid, 128>>>(msg + (size_t)base * HIDDEN, Wq,
                                            nullptr, qc, nullptr,
                                            rows, H4, HIDDEN, 0);
            }
            attn_kernel<<<rows, 128>>>(bgraph, msg, qc, base, rows);
            // nei_msg[base:] = comps_chunk @ W_h^T
            {
                dim3 grid(cdiv(HIDDEN, 64), cdiv(rows, 128));
                sgemm_kernel<<<grid, 128>>>(qc, WhT, nullptr,
                                            neimsg + (size_t)base * HIDDEN, nullptr,
                                            rows, HIDDEN, H4, 0);
            }
        }
        // per-molecule mean of nei_msg
        segmean_kernel<<<N_MOLS, 256>>>(neimsg, bond2mol, N_BONDS, HIDDEN, molmean);
        // master = relu(mol_mean @ W_mi^T + b_mi)   [8192 x 600]
        {
            dim3 grid(cdiv(MASTER_DIM, 64), cdiv(N_MOLS, 128));
            sgemm_kernel<<<grid, 128>>>(molmean, WmiT, b_mi, master, nullptr,
                                        N_MOLS, MASTER_DIM, HIDDEN, 1);
        }
        // mm = master @ W_mo^T   [8192 x 300]
        {
            dim3 grid(cdiv(HIDDEN, 64), cdiv(N_MOLS, 128));
            sgemm_kernel<<<grid, 128>>>(master, WmoT, nullptr, mm, nullptr,
                                        N_MOLS, HIDDEN, MASTER_DIM, 0);
        }
        update_kernel<<<cdiv(NB1 * HIDDEN, 256), 256>>>(bond2mol, b_mo);
    }

    // atom readout (ainp/atomh live in the qc arena; comps no longer needed)
    atom_gather_kernel<<<NA1, 128>>>(fatoms, agraph, ainp);
    {
        dim3 grid(cdiv(HIDDEN, 64), cdiv(NA1, 128));
        sgemm_kernel<<<grid, 128>>>(ainp, WoT, b_o, atomh, nullptr,
                                    NA1, HIDDEN, AIN, 1);
    }
    segmean_kernel<<<N_MOLS, 256>>>(atomh, atom2mol, N_ATOMS, HIDDEN, out);
}

// round 3
// speedup vs baseline: 2.0364x; 2.0364x over previous
#include <cuda_runtime.h>
#include <math.h>

#define N_MOLS 8192
#define N_ATOMS 98304
#define N_BONDS 196608
#define HIDDEN 300
#define HEADS 4
#define DEPTH 6
#define MASTER_DIM 600
#define ATOM_FDIM 133
#define BOND_FDIM 147
#define MAX_NB 6

#define NB1 (N_BONDS + 1)
#define NA1 (N_ATOMS + 1)
#define H4 (HEADS * HIDDEN)          /* 1200 */
#define AIN (ATOM_FDIM + HIDDEN)     /* 433 */
#define CHUNK 65664                  /* 513*128; 3 chunks cover NB1 */

/* padded K dims (multiples of 16) */
#define HID_P 304
#define BFD_P 160
#define AIN_P 448
#define MD_P  608

// ---------------------------------------------------------------------------
// Scratch (device globals). Total ~1.3GB (< host-shadow relocation limit).
// ---------------------------------------------------------------------------
__device__ float g_binput[(size_t)NB1 * HIDDEN];
__device__ float g_msg[(size_t)NB1 * HID_P];
__device__ float g_neimsg[(size_t)NB1 * HIDDEN];
__device__ float g_qc[(size_t)CHUNK * H4];     // q/comps chunk; later ainp+atomh
__device__ float g_fbp[(size_t)NB1 * BFD_P];
__device__ float g_molmean[(size_t)N_MOLS * HID_P];
__device__ float g_master[(size_t)N_MOLS * MD_P];
__device__ float g_mm[(size_t)N_MOLS * HIDDEN];

__device__ float g_WiT[BFD_P * HIDDEN];
__device__ float g_Wq[HID_P * H4];
__device__ float g_WhT[H4 * HIDDEN];           // K=1200 already mult of 16
__device__ float g_WmiT[HID_P * MASTER_DIM];
__device__ float g_WmoT[MD_P * HIDDEN];
__device__ float g_WoT[AIN_P * HIDDEN];
__device__ float g_mmpad[HIDDEN];

static_assert((size_t)CHUNK * H4 >= (size_t)NA1 * AIN_P + (size_t)NA1 * HIDDEN, "arena");

// ---------------------------------------------------------------------------
// SGEMM: C[M,N] = A[M,Kp] @ B[Kp,N] (+bias) (+relu).  Kp % 16 == 0 (padded,
// zero-filled) so the mainloop has no K guards. BM=128, BN=128, BK=16,
// 256 threads, 8x8 per thread, fma.rn.f32x2, register-staged double buffer.
// If C2: C gets raw pre-activation (ldc), C2 gets relu (ldc2).
// ---------------------------------------------------------------------------
__global__ void __launch_bounds__(256, 2) sgemm_kernel(
    const float* __restrict__ A, int lda,
    const float* __restrict__ B,
    const float* __restrict__ bias,
    float* __restrict__ C, int ldc,
    float* __restrict__ C2, int ldc2,
    int M, int N, int Kp, int do_relu)
{
    __shared__ __align__(16) float As[2][16][136];
    __shared__ __align__(16) float Bs[2][16][128];

    const int tid = threadIdx.x;
    const int bm = blockIdx.y * 128;
    const int bn = blockIdx.x * 128;
    const int m0 = (tid & 15) * 8;
    const int n0 = (tid >> 4) * 8;

    const int a_k = tid & 15;      // k within block
    const int a_m = tid >> 4;      // row group 0..15, rows a_m+16i
    const int b_n = tid & 127;     // col
    const int b_k = tid >> 7;      // 0..1, rows b_k+2i

    const float* Aptr = A + (size_t)(bm + a_m) * lda + a_k;
    const float* Bptr = B + (size_t)b_k * N + bn + b_n;
    const bool bok = (bn + b_n) < N;

    unsigned long long acc[4][8];
#pragma unroll
    for (int i = 0; i < 4; ++i)
#pragma unroll
        for (int j = 0; j < 8; ++j) acc[i][j] = 0ull;

    float ar[8], br[8];
    const int nkb = Kp >> 4;

    // prologue: load block 0
#pragma unroll
    for (int i = 0; i < 8; ++i)
        ar[i] = (bm + a_m + 16 * i < M) ? Aptr[(size_t)(16 * i) * lda] : 0.f;
#pragma unroll
    for (int i = 0; i < 8; ++i)
        br[i] = bok ? Bptr[(size_t)(2 * i) * N] : 0.f;
#pragma unroll
    for (int i = 0; i < 8; ++i) As[0][a_k][a_m + 16 * i] = ar[i];
#pragma unroll
    for (int i = 0; i < 8; ++i) Bs[0][b_k + 2 * i][b_n] = br[i];
    __syncthreads();

    for (int kb = 0; kb < nkb; ++kb) {
        const int buf = kb & 1;
        if (kb + 1 < nkb) {
            const float* Ap = Aptr + (size_t)(kb + 1) * 16;
            const float* Bp = Bptr + (size_t)(kb + 1) * 16 * N;
#pragma unroll
            for (int i = 0; i < 8; ++i)
                ar[i] = (bm + a_m + 16 * i < M) ? Ap[(size_t)(16 * i) * lda] : 0.f;
#pragma unroll
            for (int i = 0; i < 8; ++i)
                br[i] = bok ? Bp[(size_t)(2 * i) * N] : 0.f;
        }
#pragma unroll
        for (int k = 0; k < 16; ++k) {
            ulonglong2 a01 = *reinterpret_cast<const ulonglong2*>(&As[buf][k][m0]);
            ulonglong2 a23 = *reinterpret_cast<const ulonglong2*>(&As[buf][k][m0 + 4]);
            unsigned long long ap[4] = {a01.x, a01.y, a23.x, a23.y};
            float4 bu = *reinterpret_cast<const float4*>(&Bs[buf][k][n0]);
            float4 bv = *reinterpret_cast<const float4*>(&Bs[buf][k][n0 + 4]);
            float bf[8] = {bu.x, bu.y, bu.z, bu.w, bv.x, bv.y, bv.z, bv.w};
            unsigned long long bp[8];
#pragma unroll
            for (int j = 0; j < 8; ++j)
                asm("mov.b64 %0, {%1, %1};" : "=l"(bp[j]) : "r"(__float_as_uint(bf[j])));
#pragma unroll
            for (int i = 0; i < 4; ++i)
#pragma unroll
                for (int j = 0; j < 8; ++j)
                    asm("fma.rn.f32x2 %0, %1, %2, %3;"
                        : "=l"(acc[i][j])
                        : "l"(ap[i]), "l"(bp[j]), "l"(acc[i][j]));
        }
        if (kb + 1 < nkb) {
            const int nb = (kb + 1) & 1;
#pragma unroll
            for (int i = 0; i < 8; ++i) As[nb][a_k][a_m + 16 * i] = ar[i];
#pragma unroll
            for (int i = 0; i < 8; ++i) Bs[nb][b_k + 2 * i][b_n] = br[i];
            __syncthreads();
        }
    }

#pragma unroll
    for (int i = 0; i < 4; ++i) {
        int gm = bm + m0 + 2 * i;
#pragma unroll
        for (int j = 0; j < 8; ++j) {
            int gn = bn + n0 + j;
            if (gn >= N) continue;
            unsigned long long u = acc[i][j];
            float vx = __uint_as_float((unsigned)(u & 0xffffffffull));
            float vy = __uint_as_float((unsigned)(u >> 32));
            if (bias) { float bv = bias[gn]; vx += bv; vy += bv; }
            if (C2) {
                if (gm < M) {
                    C[(size_t)gm * ldc + gn] = vx;
                    C2[(size_t)gm * ldc2 + gn] = fmaxf(vx, 0.f);
                }
                if (gm + 1 < M) {
                    C[(size_t)(gm + 1) * ldc + gn] = vy;
                    C2[(size_t)(gm + 1) * ldc2 + gn] = fmaxf(vy, 0.f);
                }
            } else {
                float ox = do_relu ? fmaxf(vx, 0.f) : vx;
                float oy = do_relu ? fmaxf(vy, 0.f) : vy;
                if (gm < M)     C[(size_t)gm * ldc + gn] = ox;
                if (gm + 1 < M) C[(size_t)(gm + 1) * ldc + gn] = oy;
            }
        }
    }
}

// ---------------------------------------------------------------------------
// Weight repacking: out[c*ld_out + r] = in[r*C + c]   (in: [R,C])
// ---------------------------------------------------------------------------
__global__ void transpose_kernel(const float* __restrict__ in,
                                 float* __restrict__ out, int R, int C, int ld_out)
{
    int i = blockIdx.x * 256 + threadIdx.x;
    if (i >= R * C) return;
    int r = i / C, c = i - r * C;
    out[(size_t)c * ld_out + r] = in[i];
}

// W_ma[h,e,d] -> Wq[e][h*300+d]  (ld H4)
__global__ void wma_repack_kernel(const float* __restrict__ W_ma)
{
    int i = blockIdx.x * 256 + threadIdx.x;
    if (i >= HEADS * HIDDEN * HIDDEN) return;
    int h = i / (HIDDEN * HIDDEN);
    int r = i - h * (HIDDEN * HIDDEN);
    int e = r / HIDDEN, d = r - e * HIDDEN;
    g_Wq[(size_t)e * H4 + h * HIDDEN + d] = W_ma[i];
}

// fbonds -> padded copy (zero pad cols)
__global__ void fbp_kernel(const float* __restrict__ fbonds)
{
    size_t i = (size_t)blockIdx.x * 256 + threadIdx.x;
    if (i >= (size_t)NB1 * BFD_P) return;
    int r = (int)(i / BFD_P), c = (int)(i - (size_t)r * BFD_P);
    g_fbp[i] = (c < BOND_FDIM) ? fbonds[(size_t)r * BOND_FDIM + c] : 0.f;
}

// mm_pad[d] = sum_k relu(b_mi[k]) * W_mo[d,k]
__global__ void mmpad_kernel(const float* __restrict__ b_mi)
{
    int d = threadIdx.x;
    if (d >= HIDDEN) return;
    float s = 0.f;
    for (int k = 0; k < MASTER_DIM; ++k)
        s += fmaxf(b_mi[k], 0.f) * g_WmoT[k * HIDDEN + d];
    g_mmpad[d] = s;
}

// ---------------------------------------------------------------------------
// Attention (chunked): q/comps share qc buffer. 1 block / bond, 1 warp / head.
// ---------------------------------------------------------------------------
__global__ void __launch_bounds__(128) attn_kernel(
    const int* __restrict__ bgraph, const float* __restrict__ msg,
    float* __restrict__ qc, int base, int count)
{
    int local = blockIdx.x;
    if (local >= count) return;
    int b = base + local;
    int tid = threadIdx.x;
    __shared__ float nei[MAX_NB][HIDDEN];
    __shared__ float qsh[H4];
    __shared__ int nb[MAX_NB];

    if (tid < MAX_NB) nb[tid] = bgraph[(size_t)b * MAX_NB + tid];
    __syncthreads();

    for (int i = tid; i < MAX_NB * HIDDEN; i += 128) {
        int n = i / HIDDEN, d = i - n * HIDDEN;
        nei[n][d] = msg[(size_t)nb[n] * HID_P + d];
    }
    for (int i = tid; i < H4; i += 128) qsh[i] = qc[(size_t)local * H4 + i];
    __syncthreads();

    int w = tid >> 5, lane = tid & 31;
    float part[MAX_NB];
#pragma unroll
    for (int n = 0; n < MAX_NB; ++n) part[n] = 0.f;
    for (int d = lane; d < HIDDEN; d += 32) {
        float qv = qsh[w * HIDDEN + d];
#pragma unroll
        for (int n = 0; n < MAX_NB; ++n) part[n] += qv * nei[n][d];
    }
#pragma unroll
    for (int n = 0; n < MAX_NB; ++n)
#pragma unroll
        for (int off = 16; off > 0; off >>= 1)
            part[n] += __shfl_xor_sync(0xffffffffu, part[n], off);

    float mx = part[0];
#pragma unroll
    for (int n = 1; n < MAX_NB; ++n) mx = fmaxf(mx, part[n]);
    float e[MAX_NB], den = 0.f;
#pragma unroll
    for (int n = 0; n < MAX_NB; ++n) { e[n] = __expf(part[n] - mx); den += e[n]; }
    float inv = 1.f / den;

    for (int d = lane; d < HIDDEN; d += 32) {
        float s = 0.f;
#pragma unroll
        for (int n = 0; n < MAX_NB; ++n) s += e[n] * nei[n][d];
        qc[(size_t)local * H4 + w * HIDDEN + d] = s * inv;
    }
}

// ---------------------------------------------------------------------------
// Segment mean (sorted ids; vals has +1 padding row).
// ---------------------------------------------------------------------------
__global__ void segmean_kernel(const float* __restrict__ vals, int ldv,
                               const int* __restrict__ ids, int nitems, int D,
                               float* __restrict__ out, int ldo)
{
    int m = blockIdx.x;
    int lo = 0, hi = nitems;
    while (lo < hi) { int mid = (lo + hi) >> 1; if (ids[mid] < m) lo = mid + 1; else hi = mid; }
    int start = lo;
    hi = nitems;
    while (lo < hi) { int mid = (lo + hi) >> 1; if (ids[mid] < m + 1) lo = mid + 1; else hi = mid; }
    int end = lo;
    int cnt = end - start;
    float inv = 1.f / (float)(cnt > 1 ? cnt : 1);
    for (int d = threadIdx.x; d < D; d += blockDim.x) {
        float s = 0.f;
        for (int i = start; i < end; ++i) s += vals[(size_t)(i + 1) * ldv + d];
        out[(size_t)m * ldo + d] = s * inv;
    }
}

// msg = relu(binput + nei_msg + mm[bond2mol] + b_mo); row 0 uses mm_pad
__global__ void update_kernel(const int* __restrict__ bond2mol,
                              const float* __restrict__ b_mo)
{
    size_t idx = (size_t)blockIdx.x * 256 + threadIdx.x;
    if (idx >= (size_t)NB1 * HIDDEN) return;
    int b = (int)(idx / HIDDEN);
    int d = (int)(idx - (size_t)b * HIDDEN);
    float mmv = (b == 0) ? g_mmpad[d]
                         : g_mm[(size_t)bond2mol[b - 1] * HIDDEN + d];
    float v = g_binput[idx] + g_neimsg[idx] + mmv + b_mo[d];
    g_msg[(size_t)b * HID_P + d] = fmaxf(v, 0.f);
}

// ainp = [fatoms | sum_n msg[agraph[a,n]]]  (ld AIN_P; pads pre-zeroed)
__global__ void __launch_bounds__(128) atom_gather_kernel(
    const float* __restrict__ fatoms, const int* __restrict__ agraph,
    float* __restrict__ ainp)
{
    int a = blockIdx.x;
    __shared__ int nb[MAX_NB];
    if (threadIdx.x < MAX_NB) nb[threadIdx.x] = agraph[(size_t)a * MAX_NB + threadIdx.x];
    __syncthreads();
    for (int c = threadIdx.x; c < ATOM_FDIM; c += 128)
        ainp[(size_t)a * AIN_P + c] = fatoms[(size_t)a * ATOM_FDIM + c];
    for (int d = threadIdx.x; d < HIDDEN; d += 128) {
        float s = 0.f;
#pragma unroll
        for (int n = 0; n < MAX_NB; ++n) s += g_msg[(size_t)nb[n] * HID_P + d];
        ainp[(size_t)a * AIN_P + ATOM_FDIM + d] = s;
    }
}

// ---------------------------------------------------------------------------
// Host launch
// ---------------------------------------------------------------------------
static inline int cdiv(int a, int b) { return (a + b - 1) / b; }

static void run_gemm(const float* A, int lda, const float* B, const float* bias,
                     float* C, int ldc, float* C2, int ldc2,
                     int M, int N, int Kp, int relu)
{
    dim3 grid(cdiv(N, 128), cdiv(M, 128));
    sgemm_kernel<<<grid, 256>>>(A, lda, B, bias, C, ldc, C2, ldc2, M, N, Kp, relu);
}

extern "C" void kernel_launch(void* const* d_in, const int* in_sizes, int n_in,
                              void* d_out, int out_size)
{
    const float* fatoms   = (const float*)d_in[0];
    const float* fbonds   = (const float*)d_in[1];
    const int*   agraph   = (const int*)d_in[2];
    const int*   bgraph   = (const int*)d_in[3];
    const int*   atom2mol = (const int*)d_in[4];
    const int*   bond2mol = (const int*)d_in[5];
    const float* W_i  = (const float*)d_in[6];
    const float* W_h  = (const float*)d_in[7];
    const float* W_ma = (const float*)d_in[8];
    const float* W_mi = (const float*)d_in[9];
    const float* b_mi = (const float*)d_in[10];
    const float* W_mo = (const float*)d_in[11];
    const float* b_mo = (const float*)d_in[12];
    const float* W_o  = (const float*)d_in[13];
    const float* b_o  = (const float*)d_in[14];
    float* out = (float*)d_out;

    float *binput, *msg, *neimsg, *qc, *fbp, *molmean, *master, *mm;
    float *WiT, *Wq, *WhT, *WmiT, *WmoT, *WoT;
    cudaGetSymbolAddress((void**)&binput, g_binput);
    cudaGetSymbolAddress((void**)&msg, g_msg);
    cudaGetSymbolAddress((void**)&neimsg, g_neimsg);
    cudaGetSymbolAddress((void**)&qc, g_qc);
    cudaGetSymbolAddress((void**)&fbp, g_fbp);
    cudaGetSymbolAddress((void**)&molmean, g_molmean);
    cudaGetSymbolAddress((void**)&master, g_master);
    cudaGetSymbolAddress((void**)&mm, g_mm);
    cudaGetSymbolAddress((void**)&WiT, g_WiT);
    cudaGetSymbolAddress((void**)&Wq, g_Wq);
    cudaGetSymbolAddress((void**)&WhT, g_WhT);
    cudaGetSymbolAddress((void**)&WmiT, g_WmiT);
    cudaGetSymbolAddress((void**)&WmoT, g_WmoT);
    cudaGetSymbolAddress((void**)&WoT, g_WoT);

    float* ainp  = qc;                                  // reuse chunk arena
    float* atomh = qc + (size_t)NA1 * AIN_P;

    // zero padded buffers (pads must be 0; real data rewritten below)
    cudaMemsetAsync(WiT,  0, sizeof(float) * BFD_P * HIDDEN);
    cudaMemsetAsync(Wq,   0, sizeof(float) * HID_P * H4);
    cudaMemsetAsync(WmiT, 0, sizeof(float) * HID_P * MASTER_DIM);
    cudaMemsetAsync(WmoT, 0, sizeof(float) * MD_P * HIDDEN);
    cudaMemsetAsync(WoT,  0, sizeof(float) * AIN_P * HIDDEN);
    cudaMemsetAsync(msg,     0, sizeof(float) * (size_t)NB1 * HID_P);
    cudaMemsetAsync(molmean, 0, sizeof(float) * (size_t)N_MOLS * HID_P);
    cudaMemsetAsync(master,  0, sizeof(float) * (size_t)N_MOLS * MD_P);

    // repack weights into padded-K layouts
    transpose_kernel<<<cdiv(HIDDEN * BOND_FDIM, 256), 256>>>(W_i, WiT, HIDDEN, BOND_FDIM, HIDDEN);
    transpose_kernel<<<cdiv(HIDDEN * H4, 256), 256>>>(W_h, WhT, HIDDEN, H4, HIDDEN);
    wma_repack_kernel<<<cdiv(HEADS * HIDDEN * HIDDEN, 256), 256>>>(W_ma);
    transpose_kernel<<<cdiv(MASTER_DIM * HIDDEN, 256), 256>>>(W_mi, WmiT, MASTER_DIM, HIDDEN, MASTER_DIM);
    transpose_kernel<<<cdiv(HIDDEN * MASTER_DIM, 256), 256>>>(W_mo, WmoT, HIDDEN, MASTER_DIM, HIDDEN);
    transpose_kernel<<<cdiv(HIDDEN * AIN, 256), 256>>>(W_o, WoT, HIDDEN, AIN, HIDDEN);
    mmpad_kernel<<<1, 320>>>(b_mi);
    {
        size_t tot = (size_t)NB1 * BFD_P;
        fbp_kernel<<<(unsigned)((tot + 255) / 256), 256>>>(fbonds);
    }

    // binput = fb_pad @ WiT ; msg = relu(binput)
    run_gemm(fbp, BFD_P, WiT, nullptr, binput, HIDDEN, msg, HID_P,
             NB1, HIDDEN, BFD_P, 0);

    for (int it = 0; it < DEPTH - 1; ++it) {
        for (int base = 0; base < NB1; base += CHUNK) {
            int rows = NB1 - base; if (rows > CHUNK) rows = CHUNK;
            // q_chunk = msg[base:] @ Wq   [rows x 1200]
            run_gemm(msg + (size_t)base * HID_P, HID_P, Wq, nullptr,
                     qc, H4, nullptr, 0, rows, H4, HID_P, 0);
            attn_kernel<<<rows, 128>>>(bgraph, msg, qc, base, rows);
            // nei_msg[base:] = comps_chunk @ WhT
            run_gemm(qc, H4, WhT, nullptr,
                     neimsg + (size_t)base * HIDDEN, HIDDEN, nullptr, 0,
                     rows, HIDDEN, H4, 0);
        }
        segmean_kernel<<<N_MOLS, 256>>>(neimsg, HIDDEN, bond2mol, N_BONDS, HIDDEN,
                                        molmean, HID_P);
        run_gemm(molmean, HID_P, WmiT, b_mi, master, MD_P, nullptr, 0,
                 N_MOLS, MASTER_DIM, HID_P, 1);
        run_gemm(master, MD_P, WmoT, nullptr, mm, HIDDEN, nullptr, 0,
                 N_MOLS, HIDDEN, MD_P, 0);
        {
            size_t tot = (size_t)NB1 * HIDDEN;
            update_kernel<<<(unsigned)((tot + 255) / 256), 256>>>(bond2mol, b_mo);
        }
    }

    // atom readout (arena reuse; zero ainp pads first)
    cudaMemsetAsync(ainp, 0, sizeof(float) * (size_t)NA1 * AIN_P);
    atom_gather_kernel<<<NA1, 128>>>(fatoms, agraph, ainp);
    run_gemm(ainp, AIN_P, WoT, b_o, atomh, HIDDEN, nullptr, 0,
             NA1, HIDDEN, AIN_P, 1);
    segmean_kernel<<<N_MOLS, 256>>>(atomh, HIDDEN, atom2mol, N_ATOMS, HIDDEN,
                                    out, HIDDEN);
}